// round 5
// baseline (speedup 1.0000x reference)
#include <cuda_runtime.h>

// SplineActivation: y[b,w] = clamped cubic B-spline (16 uniform knots on [-3,3],
// degree 3) of x[b,w], per-channel coefficients coefs[w, 0..17].
//
// Round-5:
//  * Eval kernel: float4 global I/O (4 channels/thread x 4 row-groups ->
//    4x LDG.128 = 64B/thread in flight, STG.128 out), poly tile in smem with a
//    per-interval XOR swizzle (offset = ch*16 ^ ((k&7)<<4)) that keeps the
//    divergent-k LDS.128 gather ~conflict-free under channel vectorization.
//  * Build kernel unchanged from round 4 (fused FP32 matrix+apply, ~1us).

#define W_TOTAL  1024
#define B_TOTAL  8192
#define NB_IV    15
#define CH       128          // channels per block tile
#define BD       256
#define N_CTRL   18

__device__ float4 g_poly[NB_IV * W_TOTAL];   // [interval][channel] monomial cubic

// ---------------------------------------------------------------------------
// Fused build: 15x4 conversion cubics in smem (FP32), then one g_poly entry
// per thread. Grid 60 x 256.
// ---------------------------------------------------------------------------
__global__ __launch_bounds__(BD)
void build_poly_kernel(const float* __restrict__ coefs) {
    __shared__ float4 M[NB_IV * 4];
    const int t = threadIdx.x;

    if (t < NB_IV * 4) {
        const int k = t >> 2;
        const int j = t & 3;

        float tk[22];
#pragma unroll
        for (int m = 0; m < 16; m++)
            tk[3 + m] = (float)(-3.0 + (double)m * (6.0 / 15.0));
        tk[0] = tk[1] = tk[2] = tk[3];
        tk[19] = tk[20] = tk[21] = tk[18];

        const int   kg    = k + 3;
        const float x0    = tk[kg];
        const float delta = (tk[kg + 1] - tk[kg]) * (1.0f / 3.0f);
        const float Kev   = fmaf((float)k, 0.4f, -3.0f);

        float f[4];
#pragma unroll
        for (int m = 0; m < 4; m++) {
            float x = x0 + delta * (float)m;
            float left[3], right[3];
#pragma unroll
            for (int i2 = 1; i2 <= 3; i2++) {
                left [i2 - 1] = x - tk[kg + 1 - i2];
                right[i2 - 1] = tk[kg + i2] - x;
            }
            float N[4];
            N[0] = 1.0f;
#pragma unroll
            for (int jj = 1; jj <= 3; jj++) {
                float saved = 0.0f;
#pragma unroll
                for (int r = 0; r < jj; r++) {
                    float temp = N[r] / (right[r] + left[jj - 1 - r]);
                    N[r] = saved + right[r] * temp;
                    saved = left[jj - 1 - r] * temp;
                }
                N[jj] = saved;
            }
            f[m] = N[j];
        }

        const float id = 1.0f / delta;
        const float d1 = (f[1] - f[0]) * id;
        const float d2 = (f[2] - 2.0f * f[1] + f[0]) * (0.5f * id * id);
        const float d3 = (f[3] - 3.0f * f[2] + 3.0f * f[1] - f[0])
                         * ((1.0f / 6.0f) * id * id * id);
        const float a0 = f[0];
        const float a1 = d1 - delta * d2 + 2.0f * delta * delta * d3;
        const float a2 = d2 - 3.0f * delta * d3;
        const float a3 = d3;

        const float s0 = x0 - Kev;
        const float b3 = a3;
        const float b2 = a2 - 3.0f * a3 * s0;
        const float b1 = a1 - 2.0f * a2 * s0 + 3.0f * a3 * s0 * s0;
        const float b0 = a0 - a1 * s0 + a2 * s0 * s0 - a3 * s0 * s0 * s0;

        M[t] = make_float4(b0, b1, b2, b3);
    }
    __syncthreads();

    const int idx = blockIdx.x * BD + t;
    const int c   = idx & (W_TOTAL - 1);
    const int k   = idx >> 10;

    float4 acc = make_float4(0.f, 0.f, 0.f, 0.f);
#pragma unroll
    for (int j = 0; j < 4; j++) {
        float  cf = __ldg(&coefs[c * N_CTRL + k + j]);
        float4 m  = M[k * 4 + j];
        acc.x = fmaf(cf, m.x, acc.x);
        acc.y = fmaf(cf, m.y, acc.y);
        acc.z = fmaf(cf, m.z, acc.z);
        acc.w = fmaf(cf, m.w, acc.w);
    }
    g_poly[k * W_TOTAL + c] = acc;
}

// ---------------------------------------------------------------------------
// Hot kernel. 256 threads: col = t&31 owns channels c0+4*col..+3, rg = t>>5
// picks a row sub-group; R=4 unroll -> 32 rows x 128 channels per iteration.
// smem: byte offset of (k, ch) = k*2048 + (ch*16 ^ ((k&7)<<4)). XOR swizzle
// keeps divergent-k LDS.128 phases spread across banks (collision needs
// (k^k')&7 in {0,4}, ~2% for N(0,1) inputs; equal k broadcasts for free).
// ---------------------------------------------------------------------------
__device__ __forceinline__ float eval_one(float x, const char* sp_base, int chl) {
    float fi = floorf(fmaf(x, 2.5f, 7.5f));
    fi       = fminf(fmaxf(fi, 0.0f), 14.0f);
    int   k  = (int)fi;
    float s  = x - fmaf(fi, 0.4f, -3.0f);
    int  off = (k << 11) + ((chl << 4) ^ ((k & 7) << 4));
    float4 p = *(const float4*)(sp_base + off);
    return fmaf(fmaf(fmaf(p.w, s, p.z), s, p.y), s, p.x);
}

__global__ __launch_bounds__(BD, 5)
void spline_eval_kernel(const float* __restrict__ X, float* __restrict__ Y) {
    __shared__ __align__(16) char sp[NB_IV * CH * 16];   // 30,720 B
    const int t  = threadIdx.x;
    const int c0 = blockIdx.x * CH;

    // Stage poly tile with swizzle.
    for (int i = t; i < NB_IV * CH; i += BD) {
        int k   = i >> 7;
        int chl = i & (CH - 1);
        float4 v = g_poly[k * W_TOTAL + c0 + chl];
        *(float4*)(sp + (k << 11) + ((chl << 4) ^ ((k & 7) << 4))) = v;
    }
    __syncthreads();

    const int col = t & 31;            // channel group within tile
    const int rg  = t >> 5;            // row sub-group 0..7
    const int chl = col << 2;          // first local channel of this thread

    const float4* Xv = (const float4*)X;
    float4*       Yv = (float4*)Y;
    const int vrow   = W_TOTAL / 4;    // 256 float4 per row
    const int vcol   = (c0 >> 2) + col;
    const int rstep  = gridDim.y * 32;

    for (int base = blockIdx.y * 32; base < B_TOTAL; base += rstep) {
        const int r0 = base + rg;      // rows r0, r0+8, r0+16, r0+24

        float4 xv[4];
#pragma unroll
        for (int q = 0; q < 4; q++)
            xv[q] = Xv[(size_t)(r0 + 8 * q) * vrow + vcol];

#pragma unroll
        for (int q = 0; q < 4; q++) {
            float4 r;
            r.x = eval_one(xv[q].x, sp, chl + 0);
            r.y = eval_one(xv[q].y, sp, chl + 1);
            r.z = eval_one(xv[q].z, sp, chl + 2);
            r.w = eval_one(xv[q].w, sp, chl + 3);
            xv[q] = r;
        }

#pragma unroll
        for (int q = 0; q < 4; q++)
            Yv[(size_t)(r0 + 8 * q) * vrow + vcol] = xv[q];
    }
}

// ---------------------------------------------------------------------------
extern "C" void kernel_launch(void* const* d_in, const int* in_sizes, int n_in,
                              void* d_out, int out_size) {
    const float* X     = (const float*)d_in[0];
    const float* coefs = (const float*)d_in[1];
    if (n_in >= 2 && in_sizes[0] < in_sizes[1]) {   // identify by size
        X     = (const float*)d_in[1];
        coefs = (const float*)d_in[0];
    }
    float* Y = (float*)d_out;

    build_poly_kernel<<<NB_IV * W_TOTAL / BD, BD>>>(coefs);   // 60 x 256

    dim3 grid(W_TOTAL / CH, 92);       // 8 x 92 = 736 ~= 5 CTAs x 148 SMs
    spline_eval_kernel<<<grid, BD>>>(X, Y);
}

// round 6
// speedup vs baseline: 1.3053x; 1.3053x over previous
#include <cuda_runtime.h>

// SplineActivation: y[b,w] = clamped cubic B-spline (16 uniform knots on [-3,3],
// degree 3) of x[b,w], per-channel coefficients coefs[w, 0..17].
//
// Round-6: revert to round-4's scalar-channel layout (lane stride 16B -> every
// LDS.128 phase spans 32 banks, conflict-free for ANY per-lane interval), and
// attack the measured latency-boundness with an 8-deep row unroll:
// 8 independent LDG.32 per thread (1KB/warp in flight) for ~8 extra registers.
// 5 CTAs/SM x 40 warps x 1KB = 40KB load bytes in flight per SM >> the ~9KB
// needed to cover DRAM latency -> DRAM-BW-bound.
// Build kernel unchanged (fused FP32 matrix+apply, ~1.2us).

#define W_TOTAL  1024
#define B_TOTAL  8192
#define NB_IV    15
#define CH       128
#define BD       256
#define R        8            // rows per thread per iteration
#define N_CTRL   18

__device__ float4 g_poly[NB_IV * W_TOTAL];   // [interval][channel] monomial cubic

// ---------------------------------------------------------------------------
// Fused build: 15x4 conversion cubics in smem (FP32), then one g_poly entry
// per thread. Grid 60 x 256.
// ---------------------------------------------------------------------------
__global__ __launch_bounds__(BD)
void build_poly_kernel(const float* __restrict__ coefs) {
    __shared__ float4 M[NB_IV * 4];
    const int t = threadIdx.x;

    if (t < NB_IV * 4) {
        const int k = t >> 2;
        const int j = t & 3;

        float tk[22];
#pragma unroll
        for (int m = 0; m < 16; m++)
            tk[3 + m] = (float)(-3.0 + (double)m * (6.0 / 15.0));
        tk[0] = tk[1] = tk[2] = tk[3];
        tk[19] = tk[20] = tk[21] = tk[18];

        const int   kg    = k + 3;
        const float x0    = tk[kg];
        const float delta = (tk[kg + 1] - tk[kg]) * (1.0f / 3.0f);
        const float Kev   = fmaf((float)k, 0.4f, -3.0f);

        float f[4];
#pragma unroll
        for (int m = 0; m < 4; m++) {
            float x = x0 + delta * (float)m;
            float left[3], right[3];
#pragma unroll
            for (int i2 = 1; i2 <= 3; i2++) {
                left [i2 - 1] = x - tk[kg + 1 - i2];
                right[i2 - 1] = tk[kg + i2] - x;
            }
            float N[4];
            N[0] = 1.0f;
#pragma unroll
            for (int jj = 1; jj <= 3; jj++) {
                float saved = 0.0f;
#pragma unroll
                for (int r = 0; r < jj; r++) {
                    float temp = N[r] / (right[r] + left[jj - 1 - r]);
                    N[r] = saved + right[r] * temp;
                    saved = left[jj - 1 - r] * temp;
                }
                N[jj] = saved;
            }
            f[m] = N[j];
        }

        const float id = 1.0f / delta;
        const float d1 = (f[1] - f[0]) * id;
        const float d2 = (f[2] - 2.0f * f[1] + f[0]) * (0.5f * id * id);
        const float d3 = (f[3] - 3.0f * f[2] + 3.0f * f[1] - f[0])
                         * ((1.0f / 6.0f) * id * id * id);
        const float a0 = f[0];
        const float a1 = d1 - delta * d2 + 2.0f * delta * delta * d3;
        const float a2 = d2 - 3.0f * delta * d3;
        const float a3 = d3;

        const float s0 = x0 - Kev;
        const float b3 = a3;
        const float b2 = a2 - 3.0f * a3 * s0;
        const float b1 = a1 - 2.0f * a2 * s0 + 3.0f * a3 * s0 * s0;
        const float b0 = a0 - a1 * s0 + a2 * s0 * s0 - a3 * s0 * s0 * s0;

        M[t] = make_float4(b0, b1, b2, b3);
    }
    __syncthreads();

    const int idx = blockIdx.x * BD + t;
    const int c   = idx & (W_TOTAL - 1);
    const int k   = idx >> 10;

    float4 acc = make_float4(0.f, 0.f, 0.f, 0.f);
#pragma unroll
    for (int j = 0; j < 4; j++) {
        float  cf = __ldg(&coefs[c * N_CTRL + k + j]);
        float4 m  = M[k * 4 + j];
        acc.x = fmaf(cf, m.x, acc.x);
        acc.y = fmaf(cf, m.y, acc.y);
        acc.z = fmaf(cf, m.z, acc.z);
        acc.w = fmaf(cf, m.w, acc.w);
    }
    g_poly[k * W_TOTAL + c] = acc;
}

// ---------------------------------------------------------------------------
// Hot kernel. 256 threads over a 128-channel tile: ch = t&127, rl = t>>7.
// Each thread handles R=8 rows per iteration -> 16 rows per block-iteration,
// 8 independent LDG.32 in flight. smem sp[k][128] float4: k-stride = 2048B
// (multiple of 128B), lane stride 16B -> conflict-free LDS.128 for any k mix.
// Grid 8 x 92 = 736 CTAs ~= one 5-CTA/SM wave.
// ---------------------------------------------------------------------------
__global__ __launch_bounds__(BD, 5)
void spline_eval_kernel(const float* __restrict__ X, float* __restrict__ Y) {
    __shared__ float4 sp[NB_IV][CH];         // 30,720 B
    const int t  = threadIdx.x;
    const int c0 = blockIdx.x * CH;

    for (int i = t; i < NB_IV * CH; i += BD)
        ((float4*)sp)[i] = g_poly[(i >> 7) * W_TOTAL + c0 + (i & (CH - 1))];
    __syncthreads();

    const int ch = t & (CH - 1);
    const int rl = t >> 7;                   // 0..1
    const int rstep = gridDim.y * 2 * R;     // rows consumed per grid sweep

    for (int base = blockIdx.y * 2 * R; base < B_TOTAL; base += rstep) {
        const int r0 = base + rl * R;        // this thread: rows r0 .. r0+7
        const float* xp = X + (size_t)r0 * W_TOTAL + c0 + ch;
        float*       yp = Y + (size_t)r0 * W_TOTAL + c0 + ch;

        float xv[R];
#pragma unroll
        for (int q = 0; q < R; q++) xv[q] = xp[q * W_TOTAL];

#pragma unroll
        for (int q = 0; q < R; q++) {
            float x  = xv[q];
            float fi = floorf(fmaf(x, 2.5f, 7.5f));
            fi       = fminf(fmaxf(fi, 0.0f), 14.0f);
            int   k  = (int)fi;
            float s  = x - fmaf(fi, 0.4f, -3.0f);
            float4 p = sp[k][ch];
            xv[q] = fmaf(fmaf(fmaf(p.w, s, p.z), s, p.y), s, p.x);
        }

#pragma unroll
        for (int q = 0; q < R; q++) yp[q * W_TOTAL] = xv[q];
    }
}

// ---------------------------------------------------------------------------
extern "C" void kernel_launch(void* const* d_in, const int* in_sizes, int n_in,
                              void* d_out, int out_size) {
    const float* X     = (const float*)d_in[0];
    const float* coefs = (const float*)d_in[1];
    if (n_in >= 2 && in_sizes[0] < in_sizes[1]) {   // identify by size
        X     = (const float*)d_in[1];
        coefs = (const float*)d_in[0];
    }
    float* Y = (float*)d_out;

    build_poly_kernel<<<NB_IV * W_TOTAL / BD, BD>>>(coefs);   // 60 x 256

    dim3 grid(W_TOTAL / CH, 92);             // 736 CTAs ~= 5 per SM
    spline_eval_kernel<<<grid, BD>>>(X, Y);
}